// round 1
// baseline (speedup 1.0000x reference)
#include <cuda_runtime.h>

// out[b] = sum_o (x[b,:]·W[o,:] + b[o]) = x[b,:]·(sum_o W[o,:]) + sum(b)
// => column-reduce W, scalar-reduce b, then one dot per batch row.

#define IN_F   2048
#define OUT_F  8192
#define BATCH  16384
#define VEC4   (IN_F / 4)          // 512 float4 per row
#define ROW_CHUNKS 64
#define ROWS_PER_CHUNK (OUT_F / ROW_CHUNKS)   // 128

__device__ float g_partial[ROW_CHUNKS * IN_F];   // 512 KB scratch (deterministic 2-pass)
__device__ float g_wsum[IN_F];
__device__ float g_bsum;

// Pass 1: each block (bx, chunk) sums 128 rows of W for 128 float4 columns.
__global__ void wsum_partial_kernel(const float* __restrict__ W) {
    int col4  = blockIdx.x * blockDim.x + threadIdx.x;   // 0..511
    int chunk = blockIdx.y;                              // 0..63
    const float4* W4 = reinterpret_cast<const float4*>(W);
    float4 acc = make_float4(0.f, 0.f, 0.f, 0.f);
    size_t base = (size_t)chunk * ROWS_PER_CHUNK * VEC4 + col4;
    #pragma unroll 8
    for (int r = 0; r < ROWS_PER_CHUNK; r++) {
        float4 v = W4[base + (size_t)r * VEC4];
        acc.x += v.x; acc.y += v.y; acc.z += v.z; acc.w += v.w;
    }
    reinterpret_cast<float4*>(g_partial)[chunk * VEC4 + col4] = acc;
}

// Pass 2: reduce the 64 chunk partials per column.
__global__ void wsum_final_kernel() {
    int col4 = blockIdx.x * blockDim.x + threadIdx.x;    // 0..511
    const float4* P4 = reinterpret_cast<const float4*>(g_partial);
    float4 acc = make_float4(0.f, 0.f, 0.f, 0.f);
    #pragma unroll 8
    for (int c = 0; c < ROW_CHUNKS; c++) {
        float4 v = P4[c * VEC4 + col4];
        acc.x += v.x; acc.y += v.y; acc.z += v.z; acc.w += v.w;
    }
    reinterpret_cast<float4*>(g_wsum)[col4] = acc;
}

// Scalar reduce of bias (single block, deterministic tree reduce).
__global__ void bsum_kernel(const float* __restrict__ b) {
    __shared__ float sh[256];
    float s = 0.f;
    for (int i = threadIdx.x; i < OUT_F; i += 256) s += b[i];
    sh[threadIdx.x] = s;
    __syncthreads();
    #pragma unroll
    for (int o = 128; o > 0; o >>= 1) {
        if (threadIdx.x < o) sh[threadIdx.x] += sh[threadIdx.x + o];
        __syncthreads();
    }
    if (threadIdx.x == 0) g_bsum = sh[0];
}

// Main pass: one warp per batch row; w_sum staged in shared (8 KB, shared by 8 warps).
__global__ __launch_bounds__(256) void dot_kernel(const float* __restrict__ x,
                                                  float* __restrict__ out) {
    __shared__ float4 sw[VEC4];   // 8 KB
    int tid = threadIdx.x;
    const float4* Wsum4 = reinterpret_cast<const float4*>(g_wsum);
    for (int i = tid; i < VEC4; i += 256) sw[i] = Wsum4[i];
    __syncthreads();

    int warp = tid >> 5;
    int lane = tid & 31;
    int row  = blockIdx.x * 8 + warp;

    const float4* x4 = reinterpret_cast<const float4*>(x) + (size_t)row * VEC4;
    float acc = 0.f;
    #pragma unroll
    for (int k = 0; k < 16; k++) {
        float4 xv = x4[k * 32 + lane];      // coalesced 512B per warp
        float4 wv = sw[k * 32 + lane];
        acc += xv.x * wv.x;
        acc += xv.y * wv.y;
        acc += xv.z * wv.z;
        acc += xv.w * wv.w;
    }
    #pragma unroll
    for (int o = 16; o > 0; o >>= 1)
        acc += __shfl_xor_sync(0xffffffffu, acc, o);

    if (lane == 0) out[row] = acc + g_bsum;
}

extern "C" void kernel_launch(void* const* d_in, const int* in_sizes, int n_in,
                              void* d_out, int out_size) {
    const float* x = (const float*)d_in[0];   // [16384, 2048]
    const float* W = (const float*)d_in[1];   // [8192, 2048]
    const float* b = (const float*)d_in[2];   // [8192]
    float* out = (float*)d_out;               // [16384, 1]

    (void)in_sizes; (void)n_in; (void)out_size;

    wsum_partial_kernel<<<dim3(4, ROW_CHUNKS), 128>>>(W);
    wsum_final_kernel<<<4, 128>>>();
    bsum_kernel<<<1, 256>>>(b);
    dot_kernel<<<BATCH / 8, 256>>>(x, out);
}

// round 2
// speedup vs baseline: 1.1832x; 1.1832x over previous
#include <cuda_runtime.h>

// out[b] = x[b,:]·(sum_o W[o,:]) + sum(b)
// Phase 1: column-reduce W (64 MB) -> w_sum[2048]
// Phase 2: reduce partials + bias sum (tiny)
// Phase 3: one dot per batch row (128 MB)

#define IN_F   2048
#define OUT_F  8192
#define BATCH  16384
#define VEC4   (IN_F / 4)                      // 512 float4 per row
#define CHUNKS 128
#define ROWS_PER_CHUNK (OUT_F / CHUNKS)        // 64

__device__ float g_partial[CHUNKS * IN_F];     // 1 MB scratch (deterministic 2-pass)
__device__ float g_wsum[IN_F];
__device__ float g_bsum;

// ---- Pass 1: grid (2, 128) x 256 thr = 65536 threads, one full wave.
// Each thread: one col4, 64 rows, 8-way unrolled independent loads.
__global__ __launch_bounds__(256) void wsum_partial_kernel(const float* __restrict__ W) {
    int col4  = blockIdx.x * 256 + threadIdx.x;          // 0..511
    int chunk = blockIdx.y;                              // 0..127
    const float4* W4 = reinterpret_cast<const float4*>(W);
    size_t base = (size_t)chunk * ROWS_PER_CHUNK * VEC4 + col4;
    float4 acc = make_float4(0.f, 0.f, 0.f, 0.f);
    #pragma unroll 8
    for (int r = 0; r < ROWS_PER_CHUNK; r++) {
        float4 v = W4[base + (size_t)r * VEC4];
        acc.x += v.x; acc.y += v.y; acc.z += v.z; acc.w += v.w;
    }
    reinterpret_cast<float4*>(g_partial)[chunk * VEC4 + col4] = acc;
}

// ---- Pass 2: blocks 0..7 reduce 64 col4 each (4 threads/col4); block 8 sums bias.
__global__ __launch_bounds__(256) void wsum_final_kernel(const float* __restrict__ b) {
    if (blockIdx.x == 8) {
        __shared__ float sh[256];
        float s = 0.f;
        for (int i = threadIdx.x; i < OUT_F; i += 256) s += b[i];
        sh[threadIdx.x] = s;
        __syncthreads();
        #pragma unroll
        for (int o = 128; o > 0; o >>= 1) {
            if (threadIdx.x < o) sh[threadIdx.x] += sh[threadIdx.x + o];
            __syncthreads();
        }
        if (threadIdx.x == 0) g_bsum = sh[0];
        return;
    }
    int lcol = threadIdx.x & 63;                         // 0..63
    int sub  = threadIdx.x >> 6;                         // 0..3 (32 chunks each)
    int col4 = blockIdx.x * 64 + lcol;                   // 0..511
    const float4* P4 = reinterpret_cast<const float4*>(g_partial);
    float4 acc = make_float4(0.f, 0.f, 0.f, 0.f);
    #pragma unroll 8
    for (int c = 0; c < 32; c++) {
        float4 v = P4[(size_t)(sub * 32 + c) * VEC4 + col4];
        acc.x += v.x; acc.y += v.y; acc.z += v.z; acc.w += v.w;
    }
    __shared__ float4 sh4[4][64];
    sh4[sub][lcol] = acc;
    __syncthreads();
    if (sub == 0) {
        float4 a1 = sh4[1][lcol], a2 = sh4[2][lcol], a3 = sh4[3][lcol];
        acc.x += a1.x + a2.x + a3.x;
        acc.y += a1.y + a2.y + a3.y;
        acc.z += a1.z + a2.z + a3.z;
        acc.w += a1.w + a2.w + a3.w;
        reinterpret_cast<float4*>(g_wsum)[col4] = acc;
    }
}

// ---- Pass 3: 1024 blocks x 256 threads; each warp handles 2 rows (32 loads in flight).
__global__ __launch_bounds__(256) void dot_kernel(const float* __restrict__ x,
                                                  float* __restrict__ out) {
    __shared__ float4 sw[VEC4];                          // 8 KB
    int tid = threadIdx.x;
    const float4* Wsum4 = reinterpret_cast<const float4*>(g_wsum);
    sw[tid]       = Wsum4[tid];
    sw[tid + 256] = Wsum4[tid + 256];
    __syncthreads();

    int warp = tid >> 5;
    int lane = tid & 31;
    int row0 = blockIdx.x * 16 + warp * 2;

    const float4* xa = reinterpret_cast<const float4*>(x) + (size_t)row0 * VEC4 + lane;
    const float4* xb = xa + VEC4;

    float acca = 0.f, accb = 0.f;
    #pragma unroll
    for (int k = 0; k < 16; k++) {
        float4 wv = sw[k * 32 + lane];
        float4 av = xa[k * 32];
        float4 bv = xb[k * 32];
        acca += av.x * wv.x + av.y * wv.y + av.z * wv.z + av.w * wv.w;
        accb += bv.x * wv.x + bv.y * wv.y + bv.z * wv.z + bv.w * wv.w;
    }
    #pragma unroll
    for (int o = 16; o > 0; o >>= 1) {
        acca += __shfl_xor_sync(0xffffffffu, acca, o);
        accb += __shfl_xor_sync(0xffffffffu, accb, o);
    }
    if (lane == 0) {
        float bs = g_bsum;
        out[row0]     = acca + bs;
        out[row0 + 1] = accb + bs;
    }
}

extern "C" void kernel_launch(void* const* d_in, const int* in_sizes, int n_in,
                              void* d_out, int out_size) {
    const float* x = (const float*)d_in[0];   // [16384, 2048]
    const float* W = (const float*)d_in[1];   // [8192, 2048]
    const float* b = (const float*)d_in[2];   // [8192]
    float* out = (float*)d_out;               // [16384, 1]
    (void)in_sizes; (void)n_in; (void)out_size;

    wsum_partial_kernel<<<dim3(2, CHUNKS), 256>>>(W);
    wsum_final_kernel<<<9, 256>>>(b);
    dot_kernel<<<BATCH / 16, 256>>>(x, out);
}

// round 3
// speedup vs baseline: 1.2758x; 1.0783x over previous
#include <cuda_runtime.h>

// out[b] = x[b,:]·(sum_o W[o,:]) + sum(b)
// Phase 1: column-reduce W (64 MB) -> partials (2 MB)
// Phase 2: reduce partials -> w_sum[2048]; bias sum
// Phase 3: one dot per batch row (128 MB)

#define IN_F   2048
#define OUT_F  8192
#define BATCH  16384
#define VEC4   (IN_F / 4)                      // 512 float4 per row
#define CHUNKS 256
#define ROWS_PER_CHUNK (OUT_F / CHUNKS)        // 32

__device__ float g_partial[CHUNKS * IN_F];     // 2 MB scratch (deterministic 2-pass)
__device__ float g_wsum[IN_F];
__device__ float g_bsum;

// ---- Pass 1: grid (2,256)=512 blocks x 256 thr (all resident, one wave).
// Each thread: one col4, 32 rows as 4 batches of 8 EXPLICIT in-flight loads.
__global__ __launch_bounds__(256) void wsum_partial_kernel(const float* __restrict__ W) {
    int col4  = blockIdx.x * 256 + threadIdx.x;          // 0..511
    int chunk = blockIdx.y;                              // 0..255
    const float4* W4 = reinterpret_cast<const float4*>(W)
                       + (size_t)chunk * ROWS_PER_CHUNK * VEC4 + col4;
    float4 acc = make_float4(0.f, 0.f, 0.f, 0.f);
    #pragma unroll
    for (int bt = 0; bt < 4; bt++) {
        float4 v[8];
        #pragma unroll
        for (int i = 0; i < 8; i++)
            v[i] = W4[(size_t)(bt * 8 + i) * VEC4];      // 8 loads issued before any use
        #pragma unroll
        for (int i = 0; i < 8; i++) {
            acc.x += v[i].x; acc.y += v[i].y; acc.z += v[i].z; acc.w += v[i].w;
        }
    }
    reinterpret_cast<float4*>(g_partial)[chunk * VEC4 + col4] = acc;
}

// ---- Pass 2: blocks 0..7 reduce 64 col4 each (4 threads/col4, 64 chunks each);
//      block 8 sums bias.
__global__ __launch_bounds__(256) void wsum_final_kernel(const float* __restrict__ b) {
    if (blockIdx.x == 8) {
        __shared__ float sh[256];
        float s = 0.f;
        for (int i = threadIdx.x; i < OUT_F; i += 256) s += b[i];
        sh[threadIdx.x] = s;
        __syncthreads();
        #pragma unroll
        for (int o = 128; o > 0; o >>= 1) {
            if (threadIdx.x < o) sh[threadIdx.x] += sh[threadIdx.x + o];
            __syncthreads();
        }
        if (threadIdx.x == 0) g_bsum = sh[0];
        return;
    }
    int lcol = threadIdx.x & 63;                         // 0..63
    int sub  = threadIdx.x >> 6;                         // 0..3 -> 64 chunks each
    int col4 = blockIdx.x * 64 + lcol;                   // 0..511
    const float4* P4 = reinterpret_cast<const float4*>(g_partial)
                       + (size_t)(sub * 64) * VEC4 + col4;
    float4 acc = make_float4(0.f, 0.f, 0.f, 0.f);
    #pragma unroll
    for (int bt = 0; bt < 8; bt++) {
        float4 v[8];
        #pragma unroll
        for (int i = 0; i < 8; i++)
            v[i] = P4[(size_t)(bt * 8 + i) * VEC4];
        #pragma unroll
        for (int i = 0; i < 8; i++) {
            acc.x += v[i].x; acc.y += v[i].y; acc.z += v[i].z; acc.w += v[i].w;
        }
    }
    __shared__ float4 sh4[4][64];
    sh4[sub][lcol] = acc;
    __syncthreads();
    if (sub == 0) {
        float4 a1 = sh4[1][lcol], a2 = sh4[2][lcol], a3 = sh4[3][lcol];
        acc.x += a1.x + a2.x + a3.x;
        acc.y += a1.y + a2.y + a3.y;
        acc.z += a1.z + a2.z + a3.z;
        acc.w += a1.w + a2.w + a3.w;
        reinterpret_cast<float4*>(g_wsum)[col4] = acc;
    }
}

// ---- Pass 3: 2048 blocks x 256 thr; one warp per row; 2 batches of 8 explicit loads.
__global__ __launch_bounds__(256) void dot_kernel(const float* __restrict__ x,
                                                  float* __restrict__ out) {
    __shared__ float4 sw[VEC4];                          // 8 KB
    int tid = threadIdx.x;
    const float4* Wsum4 = reinterpret_cast<const float4*>(g_wsum);
    sw[tid]       = Wsum4[tid];
    sw[tid + 256] = Wsum4[tid + 256];
    __syncthreads();

    int warp = tid >> 5;
    int lane = tid & 31;
    int row  = blockIdx.x * 8 + warp;

    const float4* x4 = reinterpret_cast<const float4*>(x) + (size_t)row * VEC4 + lane;

    float acc0 = 0.f, acc1 = 0.f;
    #pragma unroll
    for (int bt = 0; bt < 2; bt++) {
        float4 v[8];
        #pragma unroll
        for (int i = 0; i < 8; i++)
            v[i] = x4[(bt * 8 + i) * 32];                // 8 loads in flight
        #pragma unroll
        for (int i = 0; i < 8; i += 2) {
            float4 w0 = sw[(bt * 8 + i) * 32 + lane];
            float4 w1 = sw[(bt * 8 + i + 1) * 32 + lane];
            acc0 += v[i].x * w0.x + v[i].y * w0.y + v[i].z * w0.z + v[i].w * w0.w;
            acc1 += v[i+1].x * w1.x + v[i+1].y * w1.y + v[i+1].z * w1.z + v[i+1].w * w1.w;
        }
    }
    float acc = acc0 + acc1;
    #pragma unroll
    for (int o = 16; o > 0; o >>= 1)
        acc += __shfl_xor_sync(0xffffffffu, acc, o);

    if (lane == 0) out[row] = acc + g_bsum;
}

extern "C" void kernel_launch(void* const* d_in, const int* in_sizes, int n_in,
                              void* d_out, int out_size) {
    const float* x = (const float*)d_in[0];   // [16384, 2048]
    const float* W = (const float*)d_in[1];   // [8192, 2048]
    const float* b = (const float*)d_in[2];   // [8192]
    float* out = (float*)d_out;               // [16384, 1]
    (void)in_sizes; (void)n_in; (void)out_size;

    wsum_partial_kernel<<<dim3(2, CHUNKS), 256>>>(W);
    wsum_final_kernel<<<9, 256>>>(b);
    dot_kernel<<<BATCH / 8, 256>>>(x, out);
}

// round 4
// speedup vs baseline: 1.2833x; 1.0059x over previous
#include <cuda_runtime.h>

// out[b] = x[b,:]·(sum_o W[o,:]) + sum(b)
// Phase 1: column-reduce W (64 MB) -> partials (4 MB), full-occupancy single wave
// Phase 2: reduce partials -> w_sum[2048]; bias sum
// Phase 3: one dot per batch row (128 MB), exactly one resident wave

#define IN_F   2048
#define OUT_F  8192
#define BATCH  16384
#define VEC4   (IN_F / 4)                      // 512 float4 per row
#define RGROUPS 512
#define ROWS_PER_RG (OUT_F / RGROUPS)          // 16

__device__ float g_partial[RGROUPS * IN_F];    // 4 MB scratch (deterministic 2-pass)
__device__ float g_wsum[IN_F];
__device__ float g_bsum;

// ---- Pass 1: grid (2,512)=1024 blocks x 256 thr = 262144 threads (~55 warps/SM).
// Each thread: one col4, 16 rows as 4 batches of 4 explicit in-flight loads.
__global__ __launch_bounds__(256, 8) void wsum_partial_kernel(const float* __restrict__ W) {
    int col4 = blockIdx.x * 256 + threadIdx.x;           // 0..511
    int rg   = blockIdx.y;                               // 0..511
    const float4* W4 = reinterpret_cast<const float4*>(W)
                       + (size_t)rg * ROWS_PER_RG * VEC4 + col4;
    float4 acc = make_float4(0.f, 0.f, 0.f, 0.f);
    #pragma unroll
    for (int bt = 0; bt < 4; bt++) {
        float4 v[4];
        #pragma unroll
        for (int i = 0; i < 4; i++)
            v[i] = W4[(size_t)(bt * 4 + i) * VEC4];      // 4 loads in flight
        #pragma unroll
        for (int i = 0; i < 4; i++) {
            acc.x += v[i].x; acc.y += v[i].y; acc.z += v[i].z; acc.w += v[i].w;
        }
    }
    reinterpret_cast<float4*>(g_partial)[rg * VEC4 + col4] = acc;
}

// ---- Pass 2: blocks 0..15 reduce 32 col4 each (8 threads/col4, 64 chunks per thread);
//      block 16 sums bias.  Reads the 4 MB partial array.
__global__ __launch_bounds__(256) void wsum_final_kernel(const float* __restrict__ b) {
    if (blockIdx.x == 16) {
        __shared__ float sh[256];
        float s = 0.f;
        for (int i = threadIdx.x; i < OUT_F; i += 256) s += b[i];
        sh[threadIdx.x] = s;
        __syncthreads();
        #pragma unroll
        for (int o = 128; o > 0; o >>= 1) {
            if (threadIdx.x < o) sh[threadIdx.x] += sh[threadIdx.x + o];
            __syncthreads();
        }
        if (threadIdx.x == 0) g_bsum = sh[0];
        return;
    }
    int lcol = threadIdx.x & 31;                         // 0..31
    int sub  = threadIdx.x >> 5;                         // 0..7 -> 64 rowgroups each
    int col4 = blockIdx.x * 32 + lcol;                   // 0..511
    const float4* P4 = reinterpret_cast<const float4*>(g_partial)
                       + (size_t)(sub * 64) * VEC4 + col4;
    float4 acc = make_float4(0.f, 0.f, 0.f, 0.f);
    #pragma unroll
    for (int bt = 0; bt < 8; bt++) {
        float4 v[8];
        #pragma unroll
        for (int i = 0; i < 8; i++)
            v[i] = P4[(size_t)(bt * 8 + i) * VEC4];
        #pragma unroll
        for (int i = 0; i < 8; i++) {
            acc.x += v[i].x; acc.y += v[i].y; acc.z += v[i].z; acc.w += v[i].w;
        }
    }
    __shared__ float4 sh4[8][32];
    sh4[sub][lcol] = acc;
    __syncthreads();
    if (sub == 0) {
        #pragma unroll
        for (int s = 1; s < 8; s++) {
            float4 a = sh4[s][lcol];
            acc.x += a.x; acc.y += a.y; acc.z += a.z; acc.w += a.w;
        }
        reinterpret_cast<float4*>(g_wsum)[col4] = acc;
    }
}

// ---- Pass 3: 1024 blocks x 256 thr (one full resident wave); each warp does
//      2 rows sequentially (16 rows per block).
__global__ __launch_bounds__(256, 8) void dot_kernel(const float* __restrict__ x,
                                                     float* __restrict__ out) {
    __shared__ float4 sw[VEC4];                          // 8 KB
    int tid = threadIdx.x;
    const float4* Wsum4 = reinterpret_cast<const float4*>(g_wsum);
    sw[tid]       = Wsum4[tid];
    sw[tid + 256] = Wsum4[tid + 256];
    __syncthreads();

    int warp = tid >> 5;
    int lane = tid & 31;
    int base = blockIdx.x * 16;

    float res[2];
    #pragma unroll
    for (int rr = 0; rr < 2; rr++) {
        int row = base + rr * 8 + warp;
        const float4* x4 = reinterpret_cast<const float4*>(x)
                           + (size_t)row * VEC4 + lane;
        float acc = 0.f;
        #pragma unroll
        for (int bt = 0; bt < 4; bt++) {
            float4 v[4];
            #pragma unroll
            for (int i = 0; i < 4; i++)
                v[i] = x4[(bt * 4 + i) * 32];            // 4 loads in flight
            #pragma unroll
            for (int i = 0; i < 4; i++) {
                float4 w = sw[(bt * 4 + i) * 32 + lane];
                acc += v[i].x * w.x + v[i].y * w.y + v[i].z * w.z + v[i].w * w.w;
            }
        }
        #pragma unroll
        for (int o = 16; o > 0; o >>= 1)
            acc += __shfl_xor_sync(0xffffffffu, acc, o);
        res[rr] = acc;
    }

    if (lane == 0) {
        float bs = g_bsum;
        out[base + warp]     = res[0] + bs;
        out[base + 8 + warp] = res[1] + bs;
    }
}

extern "C" void kernel_launch(void* const* d_in, const int* in_sizes, int n_in,
                              void* d_out, int out_size) {
    const float* x = (const float*)d_in[0];   // [16384, 2048]
    const float* W = (const float*)d_in[1];   // [8192, 2048]
    const float* b = (const float*)d_in[2];   // [8192]
    float* out = (float*)d_out;               // [16384, 1]
    (void)in_sizes; (void)n_in; (void)out_size;

    wsum_partial_kernel<<<dim3(2, RGROUPS), 256>>>(W);
    wsum_final_kernel<<<17, 256>>>(b);
    dot_kernel<<<BATCH / 16, 256>>>(x, out);
}